// round 2
// baseline (speedup 1.0000x reference)
#include <cuda_runtime.h>
#include <cstdint>

#define B_ 32
#define S_ 2048
#define E_ 512
#define H_ 512
#define G4_ 2048          // 4*H
#define NBLK 128          // recurrent CTAs
#define HP 516            // padded h row stride (floats)

typedef unsigned long long u64;

// ---------------- device scratch (no allocations allowed) ----------------
__device__ float g_xp[(size_t)S_ * G4_ * B_];   // [s][j*4+gate][b]  512MB
__device__ float g_hbuf[2][B_ * H_];
__device__ float g_hidden[B_ * H_];
__device__ volatile unsigned int g_ctr;

// ---------------- f32x2 helpers ----------------
__device__ __forceinline__ u64 ffma2(u64 a, u64 b, u64 c) {
    u64 d;
    asm("fma.rn.f32x2 %0, %1, %2, %3;" : "=l"(d) : "l"(a), "l"(b), "l"(c));
    return d;
}
__device__ __forceinline__ u64 pack2(float x, float y) {
    u64 r;
    asm("mov.b64 %0, {%1, %2};" : "=l"(r) : "f"(x), "f"(y));
    return r;
}
__device__ __forceinline__ float2 unpack2(u64 v) {
    float2 r;
    asm("mov.b64 {%0, %1}, %2;" : "=f"(r.x), "=f"(r.y) : "l"(v));
    return r;
}

// ---------------- init ----------------
__global__ void init_k() {
    int t = blockIdx.x * blockDim.x + threadIdx.x;
    if (t == 0) *(unsigned int*)&g_ctr = 0u;
    for (int i = t; i < B_ * H_; i += blockDim.x * gridDim.x)
        g_hbuf[0][i] = 0.0f;
}

// ---------------- GEMM1: x_proj = x @ W_ih^T + (b_ih + b_hh) ----------------
// A = x viewed [65536, 512] (m = b*S + s), Bmat[k][n] = W_ih[n][k]
// out layout: g_xp[((s*512 + j)*4 + gate)*32 + b], n = gate*512 + j
#define BM 128
#define BN 128
#define BK 8
__global__ void __launch_bounds__(256) gemm_xproj(
    const float* __restrict__ x, const float* __restrict__ Wih,
    const float* __restrict__ bih, const float* __restrict__ bhh)
{
    __shared__ float As[BK][BM + 4];
    __shared__ float Bs[BK][BN + 4];

    const int m0 = blockIdx.x * BM;
    const int n0 = blockIdx.y * BN;
    const int t = threadIdx.x;
    const int tx = t & 15, ty = t >> 4;

    u64 acc[8][4] = {};

    const int ldrow = t >> 1;
    const int ldkq  = (t & 1) * 4;

    for (int k0 = 0; k0 < E_; k0 += BK) {
        // load A tile (transposed into As[k][m])
        {
            float4 v = *(const float4*)&x[(size_t)(m0 + ldrow) * E_ + k0 + ldkq];
            As[ldkq + 0][ldrow] = v.x; As[ldkq + 1][ldrow] = v.y;
            As[ldkq + 2][ldrow] = v.z; As[ldkq + 3][ldrow] = v.w;
        }
        // load B tile: Bs[kk][nn] = Wih[(n0+nn)*E + k0+kk]
        {
            float4 v = *(const float4*)&Wih[(size_t)(n0 + ldrow) * E_ + k0 + ldkq];
            Bs[ldkq + 0][ldrow] = v.x; Bs[ldkq + 1][ldrow] = v.y;
            Bs[ldkq + 2][ldrow] = v.z; Bs[ldkq + 3][ldrow] = v.w;
        }
        __syncthreads();

        #pragma unroll
        for (int kk = 0; kk < BK; ++kk) {
            float4 a0 = *(const float4*)&As[kk][ty * 8];
            float4 a1 = *(const float4*)&As[kk][ty * 8 + 4];
            ulonglong2 b0 = *(const ulonglong2*)&Bs[kk][tx * 8];
            ulonglong2 b1 = *(const ulonglong2*)&Bs[kk][tx * 8 + 4];
            float av[8] = {a0.x, a0.y, a0.z, a0.w, a1.x, a1.y, a1.z, a1.w};
            u64 bv[4] = {b0.x, b0.y, b1.x, b1.y};
            #pragma unroll
            for (int i = 0; i < 8; ++i) {
                u64 ad = pack2(av[i], av[i]);
                #pragma unroll
                for (int j = 0; j < 4; ++j)
                    acc[i][j] = ffma2(ad, bv[j], acc[i][j]);
            }
        }
        __syncthreads();
    }

    // epilogue: add bias, remap to gate-interleaved layout
    const int n_base = n0 + tx * 8;
    float bias[8];
    #pragma unroll
    for (int jj = 0; jj < 8; ++jj)
        bias[jj] = bih[n_base + jj] + bhh[n_base + jj];

    const int m_base = m0 + ty * 8;
    #pragma unroll
    for (int i = 0; i < 8; ++i) {
        int m = m_base + i;
        int bidx = m >> 11;          // m / S
        int s    = m & (S_ - 1);
        size_t srow = (size_t)s * G4_;
        #pragma unroll
        for (int j = 0; j < 4; ++j) {
            float2 v = unpack2(acc[i][j]);
            int n  = n_base + 2 * j;
            {
                int jd = n & (H_ - 1), gt = n >> 9;
                g_xp[(srow + jd * 4 + gt) * B_ + bidx] = v.x + bias[2 * j];
            }
            {
                int n1 = n + 1;
                int jd = n1 & (H_ - 1), gt = n1 >> 9;
                g_xp[(srow + jd * 4 + gt) * B_ + bidx] = v.y + bias[2 * j + 1];
            }
        }
    }
}

// ---------------- persistent recurrent kernel ----------------
// 128 CTAs, each owns 4 hidden units (j0 = blockIdx.x*4), 16 gate columns.
// smem: W slice [16][512] | h [32][HP] | gates [32][17] | c [128]
#define SMEM_FLOATS (16 * 512 + 32 * HP + 32 * 17 + 128)
#define SMEM_BYTES  (SMEM_FLOATS * 4)

__global__ void __launch_bounds__(256) lstm_rec(
    const float* __restrict__ Whh, const int* __restrict__ lengths,
    float* __restrict__ out)
{
    extern __shared__ float sm[];
    float* W_s    = sm;                         // 8192
    float* h_s    = sm + 16 * 512;              // 32*516
    float* gate_s = h_s + 32 * HP;              // 544
    float* c_s    = gate_s + 32 * 17;           // 128

    const int t  = threadIdx.x;
    const int g  = blockIdx.x;
    const int j0 = g * 4;

    // load W_hh slice: row r = jl*4+gate  <-  W_hh[gate*H + j0+jl][:]
    for (int idx = t; idx < 16 * 512; idx += 256) {
        int r = idx >> 9, k = idx & 511;
        int jl = r >> 2, gate = r & 3;
        W_s[idx] = Whh[(size_t)(gate * H_ + j0 + jl) * H_ + k];
    }
    if (t < 128) c_s[t] = 0.0f;

    const int lane = t & 31;
    const int w    = t >> 5;
    const int r0   = 2 * w, r1 = 2 * w + 1;
    const int b    = lane;
    const int len_pw = (t < 128) ? lengths[t >> 2] : 0;

    __syncthreads();

    unsigned int target = 0;
    int cur = 0;

    for (int step = 0; step < S_; ++step) {
        // cooperative load of full h into smem
        const float4* hsrc = (const float4*)&g_hbuf[cur][0];
        #pragma unroll 4
        for (int i = t; i < (B_ * H_) / 4; i += 256) {
            float4 v = hsrc[i];
            int bb = i >> 7, kq = (i & 127) << 2;
            *(float4*)&h_s[bb * HP + kq] = v;
        }
        __syncthreads();

        // prefetch x_proj for this block's 2 columns
        size_t xbase = ((size_t)step * G4_ + j0 * 4);
        float xp0 = g_xp[(xbase + r0) * B_ + b];
        float xp1 = g_xp[(xbase + r1) * B_ + b];

        // dot products: cols r0, r1 over k=0..511  (f32x2 FMAs)
        u64 acc00 = 0, acc01 = 0, acc10 = 0, acc11 = 0;
        const float* hrow = &h_s[b * HP];
        const float* w0p  = &W_s[r0 * 512];
        const float* w1p  = &W_s[r1 * 512];
        #pragma unroll 16
        for (int k = 0; k < 512; k += 4) {
            ulonglong2 h2  = *(const ulonglong2*)&hrow[k];
            ulonglong2 wa2 = *(const ulonglong2*)&w0p[k];
            ulonglong2 wb2 = *(const ulonglong2*)&w1p[k];
            acc00 = ffma2(h2.x, wa2.x, acc00);
            acc01 = ffma2(h2.y, wa2.y, acc01);
            acc10 = ffma2(h2.x, wb2.x, acc10);
            acc11 = ffma2(h2.y, wb2.y, acc11);
        }
        float2 u0 = unpack2(acc00), u1 = unpack2(acc01);
        float2 u2 = unpack2(acc10), u3 = unpack2(acc11);
        gate_s[b * 17 + r0] = (u0.x + u0.y) + (u1.x + u1.y) + xp0;
        gate_s[b * 17 + r1] = (u2.x + u2.y) + (u3.x + u3.y) + xp1;
        __syncthreads();

        // pointwise gates + state update (threads 0..127: (b, jl))
        if (t < 128) {
            int bb = t >> 2, jl = t & 3;
            float gi = gate_s[bb * 17 + jl * 4 + 0];
            float gf = gate_s[bb * 17 + jl * 4 + 1];
            float gg = gate_s[bb * 17 + jl * 4 + 2];
            float go = gate_s[bb * 17 + jl * 4 + 3];
            float i_ = 1.0f / (1.0f + expf(-gi));
            float f_ = 1.0f / (1.0f + expf(-gf));
            float g_ = tanhf(gg);
            float o_ = 1.0f / (1.0f + expf(-go));
            float c  = f_ * c_s[t] + i_ * g_;
            c_s[t] = c;
            float h = o_ * tanhf(c);
            int j = j0 + jl;
            g_hbuf[cur ^ 1][bb * H_ + j] = h;
            out[((size_t)bb * S_ + step) * H_ + j] = (step < len_pw) ? h : 0.0f;
            if (step == len_pw - 1) g_hidden[bb * H_ + j] = h;
        }
        __syncthreads();

        // grid barrier (monotonic counter, release/acquire via threadfence)
        if (t == 0) {
            __threadfence();
            atomicAdd((unsigned int*)&g_ctr, 1u);
        }
        target += NBLK;
        if (t == 0) {
            while (g_ctr < target) { }
            __threadfence();
        }
        __syncthreads();
        cur ^= 1;
    }
}

// ---------------- finalize: lengths (as float) + hidden into d_out ----------------
__global__ void finalize(const int* __restrict__ lengths, float* __restrict__ d_out,
                         int out_size)
{
    const int base = B_ * S_ * H_;   // 33554432
    int t = blockIdx.x * blockDim.x + threadIdx.x;
    if (out_size >= base + B_ && t < B_)
        d_out[base + t] = (float)lengths[t];
    if (out_size >= base + B_ + B_ * H_) {
        for (int i = t; i < B_ * H_; i += blockDim.x * gridDim.x)
            d_out[base + B_ + i] = g_hidden[i];
    }
}

// ---------------- launcher ----------------
extern "C" void kernel_launch(void* const* d_in, const int* in_sizes, int n_in,
                              void* d_out, int out_size)
{
    const float* x       = (const float*)d_in[0];
    const int*   lengths = (const int*)d_in[1];
    const float* Wih     = (const float*)d_in[2];
    const float* Whh     = (const float*)d_in[3];
    const float* bih     = (const float*)d_in[4];
    const float* bhh     = (const float*)d_in[5];
    float* out = (float*)d_out;

    cudaFuncSetAttribute(lstm_rec, cudaFuncAttributeMaxDynamicSharedMemorySize,
                         SMEM_BYTES);

    init_k<<<32, 256>>>();
    dim3 g1(512, 16);
    gemm_xproj<<<g1, 256>>>(x, Wih, bih, bhh);
    lstm_rec<<<NBLK, 256, SMEM_BYTES>>>(Whh, lengths, out);
    finalize<<<64, 256>>>(lengths, out, out_size);
}

// round 3
// speedup vs baseline: 1.4169x; 1.4169x over previous
#include <cuda_runtime.h>
#include <cstdint>

#define B_ 32
#define S_ 2048
#define E_ 512
#define H_ 512
#define NBLK 128
#define WP 520
#define PSTR 33
#define GSTR 132

typedef unsigned long long u64;

// x_proj layout: [s][gate][j][b]
__device__ float g_xp[(size_t)S_ * 4 * H_ * B_];
__device__ float g_hbuf[2][B_ * H_];
__device__ float g_hidden[B_ * H_];
__device__ volatile unsigned int g_ctr;

__device__ __forceinline__ u64 ffma2(u64 a, u64 b, u64 c) {
    u64 d;
    asm("fma.rn.f32x2 %0, %1, %2, %3;" : "=l"(d) : "l"(a), "l"(b), "l"(c));
    return d;
}
__device__ __forceinline__ u64 pack2(float x, float y) {
    u64 r;
    asm("mov.b64 %0, {%1, %2};" : "=l"(r) : "f"(x), "f"(y));
    return r;
}
__device__ __forceinline__ float2 unpack2(u64 v) {
    float2 r;
    asm("mov.b64 {%0, %1}, %2;" : "=f"(r.x), "=f"(r.y) : "l"(v));
    return r;
}
__device__ __forceinline__ void cp16(uint32_t dst, const void* src) {
    asm volatile("cp.async.ca.shared.global [%0], [%1], 16;" :: "r"(dst), "l"(src));
}

__global__ void init_k() {
    int t = blockIdx.x * blockDim.x + threadIdx.x;
    if (t == 0) *(unsigned int*)&g_ctr = 0u;
    for (int i = t; i < B_ * H_; i += blockDim.x * gridDim.x)
        g_hbuf[0][i] = 0.0f;
}

// ------------- GEMM: x_proj = x @ W_ih^T + (b_ih+b_hh) -------------
// M-tile = 32 batches x 4 timesteps; N-tile = 128; BK=16 double-buffered.
__global__ void __launch_bounds__(256, 2) gemm_xproj(
    const float* __restrict__ x, const float* __restrict__ Wih,
    const float* __restrict__ bih, const float* __restrict__ bhh)
{
    __shared__ float As[2][16 * GSTR];
    __shared__ float Bs[2][16 * GSTR];

    const int t  = threadIdx.x;
    const int s0 = blockIdx.x;
    const int n0 = blockIdx.y * 128;
    const int tx = t & 15, ty = t >> 4;
    const int lr = t >> 2;
    const int lq = t & 3;

    const size_t rowA0 = (size_t)((lr & 31) * S_ + s0 * 4 + (lr >> 5)) * E_;
    const size_t rowA1 = (size_t)(((lr + 64) & 31) * S_ + s0 * 4 + ((lr + 64) >> 5)) * E_;
    const size_t rowB0 = (size_t)(n0 + lr) * E_;
    const size_t rowB1 = (size_t)(n0 + lr + 64) * E_;

    u64 acc[8][4];
    #pragma unroll
    for (int i = 0; i < 8; ++i)
        #pragma unroll
        for (int j = 0; j < 4; ++j) acc[i][j] = 0ull;

    float4 a0 = *(const float4*)&x[rowA0 + lq * 4];
    float4 a1 = *(const float4*)&x[rowA1 + lq * 4];
    float4 b0 = *(const float4*)&Wih[rowB0 + lq * 4];
    float4 b1 = *(const float4*)&Wih[rowB1 + lq * 4];
    {
        float va0[4] = {a0.x, a0.y, a0.z, a0.w};
        float va1[4] = {a1.x, a1.y, a1.z, a1.w};
        float vb0[4] = {b0.x, b0.y, b0.z, b0.w};
        float vb1[4] = {b1.x, b1.y, b1.z, b1.w};
        #pragma unroll
        for (int i = 0; i < 4; ++i) {
            As[0][(lq * 4 + i) * GSTR + lr]      = va0[i];
            As[0][(lq * 4 + i) * GSTR + lr + 64] = va1[i];
            Bs[0][(lq * 4 + i) * GSTR + lr]      = vb0[i];
            Bs[0][(lq * 4 + i) * GSTR + lr + 64] = vb1[i];
        }
    }
    __syncthreads();

    for (int st = 0; st < 32; ++st) {
        const int cb = st & 1;
        if (st < 31) {
            int k0 = (st + 1) * 16;
            a0 = *(const float4*)&x[rowA0 + k0 + lq * 4];
            a1 = *(const float4*)&x[rowA1 + k0 + lq * 4];
            b0 = *(const float4*)&Wih[rowB0 + k0 + lq * 4];
            b1 = *(const float4*)&Wih[rowB1 + k0 + lq * 4];
        }
        #pragma unroll
        for (int kk = 0; kk < 16; ++kk) {
            float4 av0 = *(const float4*)&As[cb][kk * GSTR + ty * 8];
            float4 av1 = *(const float4*)&As[cb][kk * GSTR + ty * 8 + 4];
            ulonglong2 bv0 = *(const ulonglong2*)&Bs[cb][kk * GSTR + 4 * tx];
            ulonglong2 bv1 = *(const ulonglong2*)&Bs[cb][kk * GSTR + 64 + 4 * tx];
            float av[8] = {av0.x, av0.y, av0.z, av0.w, av1.x, av1.y, av1.z, av1.w};
            u64 bb[4] = {bv0.x, bv0.y, bv1.x, bv1.y};
            #pragma unroll
            for (int i = 0; i < 8; ++i) {
                u64 ad = pack2(av[i], av[i]);
                #pragma unroll
                for (int j = 0; j < 4; ++j)
                    acc[i][j] = ffma2(ad, bb[j], acc[i][j]);
            }
        }
        if (st < 31) {
            const int nb = cb ^ 1;
            float va0[4] = {a0.x, a0.y, a0.z, a0.w};
            float va1[4] = {a1.x, a1.y, a1.z, a1.w};
            float vb0[4] = {b0.x, b0.y, b0.z, b0.w};
            float vb1[4] = {b1.x, b1.y, b1.z, b1.w};
            #pragma unroll
            for (int i = 0; i < 4; ++i) {
                As[nb][(lq * 4 + i) * GSTR + lr]      = va0[i];
                As[nb][(lq * 4 + i) * GSTR + lr + 64] = va1[i];
                Bs[nb][(lq * 4 + i) * GSTR + lr]      = vb0[i];
                Bs[nb][(lq * 4 + i) * GSTR + lr + 64] = vb1[i];
            }
        }
        __syncthreads();
    }

    float fa[8][8];
    #pragma unroll
    for (int i = 0; i < 8; ++i)
        #pragma unroll
        for (int j = 0; j < 4; ++j) {
            float2 v = unpack2(acc[i][j]);
            fa[i][2 * j] = v.x;
            fa[i][2 * j + 1] = v.y;
        }

    const int si  = ty >> 2;
    const int b0r = (ty & 3) * 8;
    const int s   = s0 * 4 + si;
    #pragma unroll
    for (int np = 0; np < 8; ++np) {
        int n = n0 + ((np < 4) ? (4 * tx + np) : (64 + 4 * tx + (np - 4)));
        float bias = bih[n] + bhh[n];
        int gt = n >> 9, jd = n & (H_ - 1);
        size_t base = ((size_t)(s * 4 + gt) * H_ + jd) * B_ + b0r;
        float4 v0 = {fa[0][np] + bias, fa[1][np] + bias, fa[2][np] + bias, fa[3][np] + bias};
        float4 v1 = {fa[4][np] + bias, fa[5][np] + bias, fa[6][np] + bias, fa[7][np] + bias};
        *(float4*)&g_xp[base]     = v0;
        *(float4*)&g_xp[base + 4] = v1;
    }
}

// ------------- persistent recurrence -------------
// 128 CTAs; CTA owns 4 hidden units (16 gate rows r=jl*4+g). Warp w = k-slice
// [64w,64w+64). Lane: cg=l&3 (rows 4ci+cg), bg=l>>2 (batches 4bg+bi).
#define SM_FLOATS (16 * WP + B_ * H_ + 8 * 16 * PSTR)
#define SMEM_REC  (SM_FLOATS * 4)

__global__ void __launch_bounds__(256, 1) lstm_rec(
    const float* __restrict__ Whh, const int* __restrict__ lengths,
    float* __restrict__ out)
{
    extern __shared__ float sm[];
    float* W_s  = sm;                 // 16*WP
    float* h_s  = sm + 16 * WP;       // 32*512, XOR-swizzled
    float* part = h_s + B_ * H_;      // 8*16*PSTR

    const int t  = threadIdx.x;
    const int w  = t >> 5;
    const int l  = t & 31;
    const int cg = l & 3;
    const int bg = l >> 2;
    const int j0 = blockIdx.x * 4;
    const int kbase = w * 64;
    const int swz = bg << 2;

    for (int idx = t; idx < 16 * 512; idx += 256) {
        int r = idx >> 9, k = idx & 511;
        W_s[r * WP + k] = Whh[(size_t)((r & 3) * H_ + j0 + (r >> 2)) * H_ + k];
    }

    const int gb  = t & 31;
    const int gjl = t >> 5;           // valid for t<128
    int len = 0;
    float c_reg = 0.0f;
    float xg[4] = {0, 0, 0, 0};
    if (t < 128) {
        len = lengths[gb];
        #pragma unroll
        for (int g = 0; g < 4; ++g)
            xg[g] = g_xp[((size_t)g * H_ + j0 + gjl) * B_ + gb];
    }
    __syncthreads();

    const uint32_t hs_b = (uint32_t)__cvta_generic_to_shared(h_s);
    unsigned int target = 0;
    int cur = 0;

    for (int step = 0; step < S_; ++step) {
        const float* hsrc = g_hbuf[cur];
        const int kk = kbase + (l & 15) * 4;
        const int bo = l >> 4;
        #pragma unroll
        for (int j = 0; j < 16; j += 2) {          // b%4 in {0,1}
            int b2 = 2 * j + bo;
            cp16(hs_b + (uint32_t)(b2 * 512 + (kk ^ ((b2 >> 2) << 2))) * 4u,
                 hsrc + b2 * H_ + kk);
        }
        asm volatile("cp.async.commit_group;");
        #pragma unroll
        for (int j = 1; j < 16; j += 2) {          // b%4 in {2,3}
            int b2 = 2 * j + bo;
            cp16(hs_b + (uint32_t)(b2 * 512 + (kk ^ ((b2 >> 2) << 2))) * 4u,
                 hsrc + b2 * H_ + kk);
        }
        asm volatile("cp.async.commit_group;");

        u64 acc[4][4];
        #pragma unroll
        for (int a = 0; a < 4; ++a)
            #pragma unroll
            for (int b = 0; b < 4; ++b) acc[a][b] = 0ull;

        asm volatile("cp.async.wait_group 1;");
        __syncwarp();
        #pragma unroll
        for (int kq = 0; kq < 16; ++kq) {
            int k  = kbase + kq * 4;
            int ks = k ^ swz;
            ulonglong2 h0 = *(const ulonglong2*)&h_s[(4 * bg + 0) * 512 + ks];
            ulonglong2 h1 = *(const ulonglong2*)&h_s[(4 * bg + 1) * 512 + ks];
            #pragma unroll
            for (int ci = 0; ci < 4; ++ci) {
                ulonglong2 wv = *(const ulonglong2*)&W_s[(4 * ci + cg) * WP + k];
                acc[ci][0] = ffma2(h0.x, wv.x, acc[ci][0]);
                acc[ci][0] = ffma2(h0.y, wv.y, acc[ci][0]);
                acc[ci][1] = ffma2(h1.x, wv.x, acc[ci][1]);
                acc[ci][1] = ffma2(h1.y, wv.y, acc[ci][1]);
            }
        }
        asm volatile("cp.async.wait_group 0;");
        __syncwarp();
        #pragma unroll
        for (int kq = 0; kq < 16; ++kq) {
            int k  = kbase + kq * 4;
            int ks = k ^ swz;
            ulonglong2 h2 = *(const ulonglong2*)&h_s[(4 * bg + 2) * 512 + ks];
            ulonglong2 h3 = *(const ulonglong2*)&h_s[(4 * bg + 3) * 512 + ks];
            #pragma unroll
            for (int ci = 0; ci < 4; ++ci) {
                ulonglong2 wv = *(const ulonglong2*)&W_s[(4 * ci + cg) * WP + k];
                acc[ci][2] = ffma2(h2.x, wv.x, acc[ci][2]);
                acc[ci][2] = ffma2(h2.y, wv.y, acc[ci][2]);
                acc[ci][3] = ffma2(h3.x, wv.x, acc[ci][3]);
                acc[ci][3] = ffma2(h3.y, wv.y, acc[ci][3]);
            }
        }

        #pragma unroll
        for (int ci = 0; ci < 4; ++ci)
            #pragma unroll
            for (int bi = 0; bi < 4; ++bi) {
                float2 v = unpack2(acc[ci][bi]);
                part[(w * 16 + 4 * ci + cg) * PSTR + 4 * bg + bi] = v.x + v.y;
            }
        __syncthreads();

        if (t < 128) {
            float gv[4];
            #pragma unroll
            for (int g = 0; g < 4; ++g) {
                float s = xg[g];
                #pragma unroll
                for (int w8 = 0; w8 < 8; ++w8)
                    s += part[(w8 * 16 + gjl * 4 + g) * PSTR + gb];
                gv[g] = s;
            }
            float i_ = 1.0f / (1.0f + expf(-gv[0]));
            float f_ = 1.0f / (1.0f + expf(-gv[1]));
            float g_ = tanhf(gv[2]);
            float o_ = 1.0f / (1.0f + expf(-gv[3]));
            c_reg = f_ * c_reg + i_ * g_;
            float h = o_ * tanhf(c_reg);
            int j = j0 + gjl;
            g_hbuf[cur ^ 1][gb * H_ + j] = h;
            out[((size_t)gb * S_ + step) * H_ + j] = (step < len) ? h : 0.0f;
            if (step == len - 1) g_hidden[gb * H_ + j] = h;
            __threadfence();
        }
        __syncthreads();

        if (t == 0) atomicAdd((unsigned int*)&g_ctr, 1u);
        target += NBLK;
        if (t < 128 && step + 1 < S_) {
            #pragma unroll
            for (int g = 0; g < 4; ++g)
                xg[g] = g_xp[((size_t)((step + 1) * 4 + g) * H_ + j0 + gjl) * B_ + gb];
        }
        if (t == 0) {
            while (g_ctr < target) { }
            __threadfence();
        }
        __syncthreads();
        cur ^= 1;
    }
}

__global__ void finalize(const int* __restrict__ lengths, float* __restrict__ d_out,
                         int out_size)
{
    const int base = B_ * S_ * H_;
    int t = blockIdx.x * blockDim.x + threadIdx.x;
    if (out_size >= base + B_ && t < B_)
        d_out[base + t] = (float)lengths[t];
    if (out_size >= base + B_ + B_ * H_) {
        for (int i = t; i < B_ * H_; i += blockDim.x * gridDim.x)
            d_out[base + B_ + i] = g_hidden[i];
    }
}

extern "C" void kernel_launch(void* const* d_in, const int* in_sizes, int n_in,
                              void* d_out, int out_size)
{
    const float* x       = (const float*)d_in[0];
    const int*   lengths = (const int*)d_in[1];
    const float* Wih     = (const float*)d_in[2];
    const float* Whh     = (const float*)d_in[3];
    const float* bih     = (const float*)d_in[4];
    const float* bhh     = (const float*)d_in[5];
    float* out = (float*)d_out;

    cudaFuncSetAttribute(lstm_rec, cudaFuncAttributeMaxDynamicSharedMemorySize,
                         SMEM_REC);

    init_k<<<32, 256>>>();
    dim3 g1(512, 16);
    gemm_xproj<<<g1, 256>>>(x, Wih, bih, bhh);
    lstm_rec<<<NBLK, 256, SMEM_REC>>>(Whh, lengths, out);
    finalize<<<64, 256>>>(lengths, out, out_size);
}